// round 5
// baseline (speedup 1.0000x reference)
#include <cuda_runtime.h>
#include <cuda_bf16.h>
#include <cfloat>
#include <math.h>

// VectorQuantizer R5: bf16 mma.sync filter + provably-lossless candidate
// pruning + exact fp32 rescore (idx bit-identical to R2 FFMA2 kernel).
// x: [65536,256] f32, codebook: [1024,256] f32.
// out: [ y (N*D) | idx as float (N) | loss | perplexity | usage | H ]

#define D 256
#define D4 64
#define KCB 1024
#define N_FIXED 65536
#define ROW_PAD 264            // bf16 row stride (528 B)
#define CAND_CAP 32

#define XS_BYTES   (128 * ROW_PAD * 2)
#define SM_XS      0
#define SM_CB0     (SM_XS + XS_BYTES)
#define SM_CB1     (SM_CB0 + XS_BYTES)
#define SM_E2      (SM_CB1 + XS_BYTES)
#define SM_RMIN    (SM_E2 + 4096)
#define SM_CCNT    (SM_RMIN + 512)
#define SM_CK      (SM_CCNT + 512)
#define SMEM_TOTAL (SM_CK + 128 * CAND_CAP * 2)   // 216064 B

__device__ int            g_idx[N_FIXED];
__device__ float          g_e2[KCB];
__device__ float          g_x2[N_FIXED];
__device__ unsigned int   g_counts[KCB];
__device__ double         g_partial[N_FIXED / 32];
__device__ __nv_bfloat16  g_cbbf[KCB * D];
__device__ unsigned int   g_e2max_bits;

__global__ void vq_init_kernel() {
    int t = threadIdx.x;
    if (t < KCB) g_counts[t] = 0u;
    if (t == 0)  g_e2max_bits = 0u;
}

// e2[k], bf16 codebook, global max e2
__global__ void vq_e2_kernel(const float* __restrict__ cb) {
    int row  = blockIdx.x * 8 + (threadIdx.x >> 5);
    int lane = threadIdx.x & 31;
    float s = 0.0f;
#pragma unroll
    for (int j = 0; j < 8; ++j) {
        int   d = lane + j * 32;
        float v = cb[row * D + d];
        g_cbbf[row * D + d] = __float2bfloat16_rn(v);
        s = fmaf(v, v, s);
    }
#pragma unroll
    for (int m = 16; m >= 1; m >>= 1)
        s += __shfl_xor_sync(0xffffffffu, s, m);
    if (lane == 0) {
        g_e2[row] = s;
        atomicMax(&g_e2max_bits, __float_as_uint(s));
    }
}

// x2 with EXACT R2 grouping: lane tx sums float4 idx tx*4+q (q asc, x,y,z,w),
// then butterfly xor 8,4,2,1 over 16 lanes.
__global__ void __launch_bounds__(256)
vq_x2_kernel(const float* __restrict__ x) {
    const int tid = threadIdx.x;
    const int tx  = tid & 15;
    const int ty  = tid >> 4;
    const int n0  = blockIdx.x * 128;
    const float4* __restrict__ x4 = (const float4*)x;
#pragma unroll
    for (int i = 0; i < 8; ++i) {
        int n = n0 + ty * 8 + i;
        float s = 0.0f;
#pragma unroll
        for (int q = 0; q < 4; ++q) {
            float4 v = x4[(size_t)n * D4 + tx * 4 + q];
            s = fmaf(v.x, v.x, s);
            s = fmaf(v.y, v.y, s);
            s = fmaf(v.z, v.z, s);
            s = fmaf(v.w, v.w, s);
        }
#pragma unroll
        for (int m = 8; m >= 1; m >>= 1)
            s += __shfl_xor_sync(0xffffffffu, s, m, 16);
        if (tx == 0) g_x2[n] = s;
    }
}

__device__ __forceinline__ unsigned int smem_u32(const void* p) {
    return (unsigned int)__cvta_generic_to_shared(p);
}
__device__ __forceinline__ void ldmatrix_x4(unsigned int* r, unsigned int a) {
    asm volatile("ldmatrix.sync.aligned.m8n8.x4.shared.b16 {%0,%1,%2,%3}, [%4];"
                 : "=r"(r[0]), "=r"(r[1]), "=r"(r[2]), "=r"(r[3]) : "r"(a));
}
__device__ __forceinline__ void mma_bf16(float* d, const unsigned int* a,
                                         unsigned int b0, unsigned int b1) {
    asm volatile(
        "mma.sync.aligned.m16n8k16.row.col.f32.bf16.bf16.f32 "
        "{%0,%1,%2,%3},{%4,%5,%6,%7},{%8,%9},{%0,%1,%2,%3};"
        : "+f"(d[0]), "+f"(d[1]), "+f"(d[2]), "+f"(d[3])
        : "r"(a[0]), "r"(a[1]), "r"(a[2]), "r"(a[3]), "r"(b0), "r"(b1));
}
__device__ __forceinline__ void cp_async16(unsigned int dst, const void* src) {
    asm volatile("cp.async.cg.shared.global [%0], [%1], 16;"
                 :: "r"(dst), "l"(src) : "memory");
}

// exact sequential fp32 dot, d=0..255 in order (matches R2 per-code chain)
__device__ __forceinline__ float seqdot256(const float* __restrict__ xr,
                                           const float* __restrict__ cr) {
    float s = 0.0f;
#pragma unroll 16
    for (int d = 0; d < 256; ++d)
        s = fmaf(__ldg(xr + d), __ldg(cr + d), s);
    return s;
}

// filter + exact select: 256 thr, 128 rows/CTA, 8 code chunks of 128.
// warps 2(row)x4(col): warp tile 64 rows x 32 codes via m16n8k16.
__global__ void __launch_bounds__(256, 1)
vq_filter_kernel(const float* __restrict__ x, const float* __restrict__ cb) {
    extern __shared__ char smem[];
    __nv_bfloat16*  xs  = (__nv_bfloat16*)(smem + SM_XS);
    float*          e2s = (float*)(smem + SM_E2);
    int*            rmn = (int*)(smem + SM_RMIN);
    int*            cnt = (int*)(smem + SM_CCNT);
    unsigned short* ck  = (unsigned short*)(smem + SM_CK);

    const int tid  = threadIdx.x;
    const int lane = tid & 31;
    const int w    = tid >> 5;
    const int wr   = w >> 2;
    const int wc   = w & 3;
    const int n0   = blockIdx.x * 128;

    for (int i = tid; i < KCB; i += 256) e2s[i] = g_e2[i];
    for (int i = tid; i < 128; i += 256) { rmn[i] = 0x7F7FFFFF; cnt[i] = 0; }

    // prefetch code chunk 0
    {
        unsigned int dst0 = smem_u32(smem + SM_CB0);
#pragma unroll
        for (int u = 0; u < 16; ++u) {
            int op = tid + u * 256;
            int row = op >> 5, seg = op & 31;
            cp_async16(dst0 + row * (ROW_PAD * 2) + seg * 16,
                       &g_cbbf[(size_t)row * D + seg * 8]);
        }
        asm volatile("cp.async.commit_group;" ::: "memory");
    }

    // x tile f32 -> bf16 smem
    {
        const float4* __restrict__ x4 = (const float4*)x;
#pragma unroll
        for (int u = 0; u < 32; ++u) {
            int f = tid + u * 256;
            int r = f >> 6, c4 = f & 63;
            float4 v = x4[(size_t)(n0 + r) * D4 + c4];
            __nv_bfloat162 lo(__float2bfloat16_rn(v.x), __float2bfloat16_rn(v.y));
            __nv_bfloat162 hi(__float2bfloat16_rn(v.z), __float2bfloat16_rn(v.w));
            *(__nv_bfloat162*)(&xs[r * ROW_PAD + c4 * 4])     = lo;
            *(__nv_bfloat162*)(&xs[r * ROW_PAD + c4 * 4 + 2]) = hi;
        }
    }

    const float e2max = __uint_as_float(g_e2max_bits);
    float x2A[4], x2B[4], tauA[4], tauB[4];
#pragma unroll
    for (int mf = 0; mf < 4; ++mf) {
        int rA = wr * 64 + mf * 16 + (lane >> 2);
        x2A[mf] = g_x2[n0 + rA];
        x2B[mf] = g_x2[n0 + rA + 8];
        tauA[mf] = 0.0390625f * sqrtf(x2A[mf] * e2max);   // 2.5 * 2^-6
        tauB[mf] = 0.0390625f * sqrtf(x2B[mf] * e2max);
    }

    unsigned int xs_base = smem_u32(smem + SM_XS);
    unsigned int cbb0 = smem_u32(smem + SM_CB0);
    unsigned int cbb1 = smem_u32(smem + SM_CB1);
    unsigned int aoff[4];
#pragma unroll
    for (int mf = 0; mf < 4; ++mf) {
        int row = wr * 64 + mf * 16 + (lane & 7) + ((lane >> 3) & 1) * 8;
        aoff[mf] = xs_base + (row * ROW_PAD + (lane >> 4) * 8) * 2;
    }
    unsigned int boff[2];
#pragma unroll
    for (int g = 0; g < 2; ++g) {
        int row  = wc * 32 + g * 16 + (lane & 7) + ((lane >> 4) << 3);
        boff[g] = (row * ROW_PAD + ((lane >> 3) & 1) * 8) * 2;
    }

    __syncthreads();

    float acc[4][4][4];

#pragma unroll 1
    for (int nk = 0; nk < 8; ++nk) {
        if (nk < 7) {
            unsigned int dst = (nk & 1) ? cbb0 : cbb1;   // next buffer
#pragma unroll
            for (int u = 0; u < 16; ++u) {
                int op = tid + u * 256;
                int row = op >> 5, seg = op & 31;
                cp_async16(dst + row * (ROW_PAD * 2) + seg * 16,
                           &g_cbbf[(size_t)((nk + 1) * 128 + row) * D + seg * 8]);
            }
            asm volatile("cp.async.commit_group;" ::: "memory");
            asm volatile("cp.async.wait_group 1;" ::: "memory");
        } else {
            asm volatile("cp.async.wait_group 0;" ::: "memory");
        }
        __syncthreads();

#pragma unroll
        for (int mf = 0; mf < 4; ++mf)
#pragma unroll
            for (int nf = 0; nf < 4; ++nf)
#pragma unroll
                for (int j = 0; j < 4; ++j) acc[mf][nf][j] = 0.0f;

        unsigned int cbb = (nk & 1) ? cbb1 : cbb0;
#pragma unroll 4
        for (int kk = 0; kk < 16; ++kk) {
            unsigned int a[4][4], b[2][4];
#pragma unroll
            for (int mf = 0; mf < 4; ++mf) ldmatrix_x4(a[mf], aoff[mf] + kk * 32);
#pragma unroll
            for (int g = 0; g < 2; ++g)    ldmatrix_x4(b[g], cbb + boff[g] + kk * 32);
#pragma unroll
            for (int mf = 0; mf < 4; ++mf) {
                mma_bf16(acc[mf][0], a[mf], b[0][0], b[0][1]);
                mma_bf16(acc[mf][1], a[mf], b[0][2], b[0][3]);
                mma_bf16(acc[mf][2], a[mf], b[1][0], b[1][1]);
                mma_bf16(acc[mf][3], a[mf], b[1][2], b[1][3]);
            }
        }

        // approx dist + running row-min
#pragma unroll
        for (int mf = 0; mf < 4; ++mf) {
            float mnA = FLT_MAX, mnB = FLT_MAX;
#pragma unroll
            for (int nf = 0; nf < 4; ++nf) {
#pragma unroll
                for (int j0 = 0; j0 < 2; ++j0) {
                    int k = nk * 128 + wc * 32 + nf * 8 + (lane & 3) * 2 + j0;
                    float e2v = e2s[k];
                    float dA = __fadd_rn(__fadd_rn(x2A[mf], e2v),
                                         -__fmul_rn(2.0f, acc[mf][nf][j0]));
                    float dB = __fadd_rn(__fadd_rn(x2B[mf], e2v),
                                         -__fmul_rn(2.0f, acc[mf][nf][j0 + 2]));
                    acc[mf][nf][j0]     = dA;
                    acc[mf][nf][j0 + 2] = dB;
                    mnA = fminf(mnA, dA);
                    mnB = fminf(mnB, dB);
                }
            }
#pragma unroll
            for (int m = 1; m <= 2; m <<= 1) {
                mnA = fminf(mnA, __shfl_xor_sync(0xffffffffu, mnA, m));
                mnB = fminf(mnB, __shfl_xor_sync(0xffffffffu, mnB, m));
            }
            if ((lane & 3) == 0) {
                int rA = wr * 64 + mf * 16 + (lane >> 2);
                atomicMin(&rmn[rA],     __float_as_int(mnA));
                atomicMin(&rmn[rA + 8], __float_as_int(mnB));
            }
        }
        __syncthreads();

        // candidate collection (running min only shrinks -> never misses)
#pragma unroll
        for (int mf = 0; mf < 4; ++mf) {
            int rA = wr * 64 + mf * 16 + (lane >> 2);
            float thA = __int_as_float(rmn[rA])     + tauA[mf];
            float thB = __int_as_float(rmn[rA + 8]) + tauB[mf];
#pragma unroll
            for (int nf = 0; nf < 4; ++nf) {
#pragma unroll
                for (int j0 = 0; j0 < 2; ++j0) {
                    int k = nk * 128 + wc * 32 + nf * 8 + (lane & 3) * 2 + j0;
                    if (acc[mf][nf][j0] <= thA) {
                        int p = atomicAdd(&cnt[rA], 1);
                        if (p < CAND_CAP) ck[rA * CAND_CAP + p] = (unsigned short)k;
                    }
                    if (acc[mf][nf][j0 + 2] <= thB) {
                        int p = atomicAdd(&cnt[rA + 8], 1);
                        if (p < CAND_CAP) ck[(rA + 8) * CAND_CAP + p] = (unsigned short)k;
                    }
                }
            }
        }
        __syncthreads();
    }

    // exact selection: quad of lanes per row
#pragma unroll 1
    for (int batch = 0; batch < 2; ++batch) {
        int r  = w * 16 + batch * 8 + (lane >> 2);
        int li = lane & 3;
        int n  = n0 + r;
        int c  = cnt[r];
        const float* xr = x + (size_t)n * D;
        float x2v = g_x2[n];

        float bd = FLT_MAX;
        int   bk = 0x7fffffff;
        if (c <= CAND_CAP) {
            for (int j = li; j < c; j += 4) {
                int k = ck[r * CAND_CAP + j];
                float s  = seqdot256(xr, cb + (size_t)k * D);
                float dd = __fadd_rn(__fadd_rn(x2v, e2s[k]),
                                     -__fmul_rn(2.0f, s));
                if (dd < bd || (dd == bd && k < bk)) { bd = dd; bk = k; }
            }
        } else {   // overflow fallback: exact full scan (deterministic)
            for (int k = li; k < KCB; k += 4) {
                float s  = seqdot256(xr, cb + (size_t)k * D);
                float dd = __fadd_rn(__fadd_rn(x2v, e2s[k]),
                                     -__fmul_rn(2.0f, s));
                if (dd < bd || (dd == bd && k < bk)) { bd = dd; bk = k; }
            }
        }
#pragma unroll
        for (int m = 1; m <= 2; m <<= 1) {
            float od = __shfl_xor_sync(0xffffffffu, bd, m);
            int   ok = __shfl_xor_sync(0xffffffffu, bk, m);
            if (od < bd || (od == bd && ok < bk)) { bd = od; bk = ok; }
        }
        if (li == 0) g_idx[n] = bk;
    }
}

// gather (unchanged from R2): warp per 4 rows; y = fl(x + fl(q-x));
// f64 partials; histogram; idx output.
__global__ void __launch_bounds__(256)
vq_gather_kernel(const float* __restrict__ x, const float* __restrict__ cb,
                 float* __restrict__ y_out, float* __restrict__ idxf_out) {
    __shared__ double wsum[8];
    const int tid  = threadIdx.x;
    const int wid  = tid >> 5;
    const int lane = tid & 31;
    const int nb   = blockIdx.x * 32 + wid * 4;

    int k4[4];
#pragma unroll
    for (int rr = 0; rr < 4; ++rr) k4[rr] = g_idx[nb + rr];

    const float4* x4  = (const float4*)x;
    const float4* cb4 = (const float4*)cb;
    float4* y4 = (float4*)y_out;

    double acc = 0.0;
#pragma unroll
    for (int rr = 0; rr < 4; ++rr) {
        int n = nb + rr;
        int k = k4[rr];
#pragma unroll
        for (int u = 0; u < 2; ++u) {
            int d4 = lane + u * 32;
            float4 xv = x4[(size_t)n * D4 + d4];
            float4 qv = cb4[(size_t)k * D4 + d4];
            float tx_ = __fadd_rn(qv.x, -xv.x);
            float ty_ = __fadd_rn(qv.y, -xv.y);
            float tz_ = __fadd_rn(qv.z, -xv.z);
            float tw_ = __fadd_rn(qv.w, -xv.w);
            float4 yv;
            yv.x = __fadd_rn(xv.x, tx_);
            yv.y = __fadd_rn(xv.y, ty_);
            yv.z = __fadd_rn(xv.z, tz_);
            yv.w = __fadd_rn(xv.w, tw_);
            y4[(size_t)n * D4 + d4] = yv;
            acc += (double)tx_ * tx_ + (double)ty_ * ty_ +
                   (double)tz_ * tz_ + (double)tw_ * tw_;
        }
        if (lane == 0) {
            atomicAdd(&g_counts[k], 1u);
            if (idxf_out) idxf_out[n] = (float)k;
        }
    }

#pragma unroll
    for (int m = 16; m >= 1; m >>= 1)
        acc += __shfl_xor_sync(0xffffffffu, acc, m);
    if (lane == 0) wsum[wid] = acc;
    __syncthreads();
    if (tid == 0) {
        double s = 0.0;
#pragma unroll
        for (int i = 0; i < 8; ++i) s += wsum[i];
        g_partial[blockIdx.x] = s;
    }
}

__global__ void __launch_bounds__(1024)
vq_finalize_kernel(float* __restrict__ scal_out, int nblocks_gather) {
    __shared__ double redH[1024];
    __shared__ double redU[1024];
    __shared__ double redS[1024];
    int t = threadIdx.x;

    double s = 0.0;
    for (int i = t; i < nblocks_gather; i += 1024) s += g_partial[i];

    float p    = (float)g_counts[t] * (1.0f / 65536.0f);
    float term = p * log2f(p + 1e-10f);

    redH[t] = -(double)term;
    redU[t] = (p > 0.0f) ? 1.0 : 0.0;
    redS[t] = s;
    __syncthreads();
#pragma unroll
    for (int m = 512; m >= 1; m >>= 1) {
        if (t < m) {
            redH[t] += redH[t + m];
            redU[t] += redU[t + m];
            redS[t] += redS[t + m];
        }
        __syncthreads();
    }
    if (t == 0) {
        double mse  = redS[0] / (double)((size_t)N_FIXED * D);
        float  c     = (float)mse;
        float  loss  = __fadd_rn(__fmul_rn(0.25f, c), c);
        float  H     = (float)redH[0];
        float  perp  = expf(__fmul_rn(H, 0.69314718f));
        float  usage = (float)(redU[0] / 1024.0);
        scal_out[0] = loss;
        scal_out[1] = perp;
        scal_out[2] = usage;
        scal_out[3] = H;
    }
}

extern "C" void kernel_launch(void* const* d_in, const int* in_sizes, int n_in,
                              void* d_out, int out_size) {
    (void)n_in;
    const float* x  = (const float*)d_in[0];
    const float* cb = (const float*)d_in[1];
    float* out = (float*)d_out;

    const int    n  = in_sizes[0] / D;      // 65536
    const size_t ND = (size_t)n * D;

    const long long os = (long long)out_size;
    const int with_idx  = os >= (long long)(ND + (size_t)n);
    const int with_scal = os >= (long long)(ND + (size_t)n + 4);

    cudaFuncSetAttribute(vq_filter_kernel,
                         cudaFuncAttributeMaxDynamicSharedMemorySize,
                         SMEM_TOTAL);

    vq_init_kernel<<<1, 1024>>>();
    vq_e2_kernel<<<KCB / 8, 256>>>(cb);
    vq_x2_kernel<<<n / 128, 256>>>(x);
    vq_filter_kernel<<<n / 128, 256, SMEM_TOTAL>>>(x, cb);
    vq_gather_kernel<<<n / 32, 256>>>(x, cb, out,
                                      with_idx ? (out + ND) : (float*)0);
    if (with_scal)
        vq_finalize_kernel<<<1, 1024>>>(out + ND + n, n / 32);
}